// round 13
// baseline (speedup 1.0000x reference)
#include <cuda_runtime.h>
#include <cuda_fp16.h>
#include <cstdint>
#include <math.h>

#define TOKENS 32768
#define EDIM   512
#define FFN    2048
#define NQ     8
#define HALF_TOKENS (TOKENS / 2)

// ---------------- scratch (device globals: allowed) ----------------
__device__ __half g_W2h[EDIM * FFN];           // 2 MB
__device__ __half g_Hh[(size_t)TOKENS * FFN];  // 128 MB

// ---------------- prep: W2 -> fp16 ----------------
__global__ void __launch_bounds__(256) prep_kernel(const float* __restrict__ W2) {
    int i = (blockIdx.x * blockDim.x + threadIdx.x) * 4;
    float4 v = *reinterpret_cast<const float4*>(W2 + i);
    __half2* dst = reinterpret_cast<__half2*>(g_W2h + i);
    dst[0] = __floats2half2_rn(v.x, v.y);
    dst[1] = __floats2half2_rn(v.z, v.w);
}

// ---------------- h kernel: h = relu(q @ W1^T + b1), fp16, f32x2 packed ----------------
// 256 threads, 32 tokens/block. Thread owns outputs f0..f0+7 as 4 packed pairs.
__global__ void __launch_bounds__(256)
h_kernel(const float* __restrict__ x, const float* __restrict__ theta,
         const float* __restrict__ W1, const float* __restrict__ b1, int mbase)
{
    __shared__ float qv[32][8];
    const int tid = threadIdx.x;
    const int m0  = mbase + blockIdx.x * 32;

    {
        int m = tid >> 3, q = tid & 7;
        qv[m][q] = cosf(x[(size_t)(m0 + m) * EDIM + q]) * cosf(theta[q]);
    }
    __syncthreads();

    const int f0 = tid * 8;
    // w2[i][q] = pack(W1[f0+2i][q], W1[f0+2i+1][q]); bb2[i] = pack(b1 pair)
    unsigned long long w2[4][8], bb2[4];
    #pragma unroll
    for (int i = 0; i < 4; i++) {
        const float4* p0 = reinterpret_cast<const float4*>(W1 + (size_t)(f0 + 2 * i) * NQ);
        const float4* p1 = reinterpret_cast<const float4*>(W1 + (size_t)(f0 + 2 * i + 1) * NQ);
        float4 a0 = p0[0], b0 = p0[1];
        float4 a1 = p1[0], b1v = p1[1];
        float r0[8] = {a0.x, a0.y, a0.z, a0.w, b0.x, b0.y, b0.z, b0.w};
        float r1[8] = {a1.x, a1.y, a1.z, a1.w, b1v.x, b1v.y, b1v.z, b1v.w};
        #pragma unroll
        for (int q = 0; q < 8; q++)
            asm("mov.b64 %0, {%1,%2};" : "=l"(w2[i][q]) : "f"(r0[q]), "f"(r1[q]));
        asm("mov.b64 %0, {%1,%2};" : "=l"(bb2[i]) : "f"(b1[f0 + 2 * i]), "f"(b1[f0 + 2 * i + 1]));
    }

    for (int m = 0; m < 32; m++) {
        unsigned long long q2[8];
        #pragma unroll
        for (int q = 0; q < 8; q++) {
            float qs = qv[m][q];
            asm("mov.b64 %0, {%1,%1};" : "=l"(q2[q]) : "f"(qs));
        }
        unsigned long long a2[4];
        #pragma unroll
        for (int i = 0; i < 4; i++) a2[i] = bb2[i];
        #pragma unroll
        for (int q = 0; q < 8; q++)
            #pragma unroll
            for (int i = 0; i < 4; i++)
                asm("fma.rn.f32x2 %0, %1, %2, %0;" : "+l"(a2[i]) : "l"(q2[q]), "l"(w2[i][q]));

        uint32_t p[4];
        #pragma unroll
        for (int i = 0; i < 4; i++) {
            float lo, hi;
            asm("mov.b64 {%0,%1}, %2;" : "=f"(lo), "=f"(hi) : "l"(a2[i]));
            lo = fmaxf(lo, 0.0f);
            hi = fmaxf(hi, 0.0f);
            asm("cvt.rn.f16x2.f32 %0, %1, %2;" : "=r"(p[i]) : "f"(hi), "f"(lo));
        }
        __half* dst = g_Hh + (size_t)(m0 + m) * FFN + f0;
        asm volatile("st.global.v4.b32 [%0], {%1,%2,%3,%4};"
                     :: "l"(dst), "r"(p[0]), "r"(p[1]), "r"(p[2]), "r"(p[3]) : "memory");
    }
}

// ---------------- GEMM: out = H @ W2^T + b2 (unchanged proven core) ----------------
#define BM 128
#define BN 128
#define BK 64
#define GT 256
#define STAGES 3
#define CHUNKS (FFN / BK)   // 32
#define STAGE_BYTES 32768
#define SMEM_TOTAL (STAGES * STAGE_BYTES)   // 96 KB

__device__ __forceinline__ uint32_t s2u(const void* p) {
    uint32_t a;
    asm("{ .reg .u64 t; cvta.to.shared.u64 t, %1; cvt.u32.u64 %0, t; }" : "=r"(a) : "l"(p));
    return a;
}
#define LDSM_X4(r, addr) \
    asm volatile("ldmatrix.sync.aligned.m8n8.x4.shared.b16 {%0,%1,%2,%3}, [%4];" \
        : "=r"((r)[0]), "=r"((r)[1]), "=r"((r)[2]), "=r"((r)[3]) : "r"(addr))

__device__ __forceinline__ void mma_f16(float* d, const uint32_t* a, uint32_t b0, uint32_t b1) {
    asm volatile(
        "mma.sync.aligned.m16n8k16.row.col.f32.f16.f16.f32 "
        "{%0,%1,%2,%3}, {%4,%5,%6,%7}, {%8,%9}, {%0,%1,%2,%3};"
        : "+f"(d[0]), "+f"(d[1]), "+f"(d[2]), "+f"(d[3])
        : "r"(a[0]), "r"(a[1]), "r"(a[2]), "r"(a[3]), "r"(b0), "r"(b1));
}

__global__ void __launch_bounds__(GT, 2)
gemm_kernel(const float* __restrict__ b2, float* __restrict__ out, int mbase)
{
    extern __shared__ unsigned char smem[];
    const uint32_t sb = s2u(smem);
    const int tid  = threadIdx.x;
    const int warp = tid >> 5;
    const int lane = tid & 31;
    const int g  = lane >> 2;
    const int tg = lane & 3;

    const int m0 = mbase + blockIdx.x * BM;
    const int n0 = blockIdx.y * BN;

    const int wm = (warp >> 2) * 64;
    const int wn = (warp & 3) * 32;

    const int ar  = (lane & 7) + ((lane >> 3) & 1) * 8;
    const int ac8 = ((lane >> 4) & 1) * 8;
    const int br  = (lane & 7) + ((lane >> 4) & 1) * 8;
    const int bc8 = ((lane >> 3) & 1) * 8;

    float acc[4][4][4];
    #pragma unroll
    for (int mi = 0; mi < 4; mi++)
        #pragma unroll
        for (int ni = 0; ni < 4; ni++)
            #pragma unroll
            for (int r = 0; r < 4; r++)
                acc[mi][ni][r] = 0.0f;

    auto produce = [&](int c, int slot) {
        const uint32_t aB = sb + slot * STAGE_BYTES;
        const uint32_t bB = aB + 16384;
        #pragma unroll
        for (int i = 0; i < 8; i++) {
            int idx = tid + i * GT;
            int row = (idx >> 3) & 127;
            int kq  = idx & 7;
            uint32_t off = (uint32_t)row * 128 + (((uint32_t)kq * 16) ^ ((row & 7) << 4));
            if (idx < 1024) {
                const __half* src = g_Hh + (size_t)(m0 + row) * FFN + c * BK + kq * 8;
                asm volatile("cp.async.cg.shared.global [%0], [%1], 16;"
                             :: "r"(aB + off), "l"(src) : "memory");
            } else {
                const __half* src = g_W2h + (size_t)(n0 + row) * FFN + c * BK + kq * 8;
                asm volatile("cp.async.cg.shared.global [%0], [%1], 16;"
                             :: "r"(bB + off), "l"(src) : "memory");
            }
        }
        asm volatile("cp.async.commit_group;" ::: "memory");
    };

    auto consume = [&](int slot) {
        const uint32_t aB = sb + slot * STAGE_BYTES;
        const uint32_t bB = aB + 16384;
        #pragma unroll
        for (int ks = 0; ks < 4; ks++) {
            int kb = ks * 16;
            uint32_t afr[4][4];
            #pragma unroll
            for (int mi = 0; mi < 4; mi++) {
                int r = wm + mi * 16 + ar;
                uint32_t cb = (uint32_t)(kb + ac8) * 2;
                LDSM_X4(afr[mi], aB + (uint32_t)r * 128 + (cb ^ ((r & 7) << 4)));
            }
            uint32_t bfr[2][4];
            #pragma unroll
            for (int p = 0; p < 2; p++) {
                int n = wn + p * 16 + br;
                uint32_t cb = (uint32_t)(kb + bc8) * 2;
                LDSM_X4(bfr[p], bB + (uint32_t)n * 128 + (cb ^ ((n & 7) << 4)));
            }
            #pragma unroll
            for (int ni = 0; ni < 4; ni++) {
                uint32_t b0 = bfr[ni >> 1][(ni & 1) * 2 + 0];
                uint32_t b1 = bfr[ni >> 1][(ni & 1) * 2 + 1];
                #pragma unroll
                for (int mi = 0; mi < 4; mi++)
                    mma_f16(acc[mi][ni], afr[mi], b0, b1);
            }
        }
    };

    produce(0, 0);
    produce(1, 1);

    #pragma unroll 1
    for (int c = 0; c < CHUNKS - 1; c++) {
        asm volatile("cp.async.wait_group 1;" ::: "memory");
        __syncthreads();
        consume(c % STAGES);
        if (c + 2 < CHUNKS) produce(c + 2, (c + 2) % STAGES);
    }
    asm volatile("cp.async.wait_group 0;" ::: "memory");
    __syncthreads();
    consume((CHUNKS - 1) % STAGES);

    #pragma unroll
    for (int mi = 0; mi < 4; mi++) {
        #pragma unroll
        for (int ni = 0; ni < 4; ni++) {
            int row = m0 + wm + mi * 16 + g;
            int col = n0 + wn + ni * 8 + 2 * tg;
            float b2a = b2[col];
            float b2b = b2[col + 1];
            float2 v0 = make_float2(acc[mi][ni][0] + b2a, acc[mi][ni][1] + b2b);
            float2 v1 = make_float2(acc[mi][ni][2] + b2a, acc[mi][ni][3] + b2b);
            *reinterpret_cast<float2*>(out + (size_t)row * EDIM + col)       = v0;
            *reinterpret_cast<float2*>(out + (size_t)(row + 8) * EDIM + col) = v1;
        }
    }
}

extern "C" void kernel_launch(void* const* d_in, const int* in_sizes, int n_in,
                              void* d_out, int out_size) {
    const float* x     = (const float*)d_in[0];
    const float* theta = (const float*)d_in[1];
    const float* W1    = (const float*)d_in[2];
    const float* b1    = (const float*)d_in[3];
    const float* W2    = (const float*)d_in[4];
    const float* b2    = (const float*)d_in[5];
    float* out = (float*)d_out;

    cudaFuncSetAttribute(gemm_kernel,
                         cudaFuncAttributeMaxDynamicSharedMemorySize, SMEM_TOTAL);

    dim3 ggrid(HALF_TOKENS / BM, EDIM / BN);   // (128, 4) per half

    // Try fork-join overlap: gemm(half0) on side stream overlaps h(half1).
    // Streams/events created fresh per call (no static guards) and leaked —
    // kernel_launch runs only a handful of times (correctness + capture).
    cudaStream_t s2 = nullptr;
    cudaEvent_t eFork = nullptr, eJoin = nullptr;
    bool ok = (cudaStreamCreateWithFlags(&s2, cudaStreamNonBlocking) == cudaSuccess)
           && (cudaEventCreateWithFlags(&eFork, cudaEventDisableTiming) == cudaSuccess)
           && (cudaEventCreateWithFlags(&eJoin, cudaEventDisableTiming) == cudaSuccess);

    prep_kernel<<<(EDIM * FFN / 4) / 256, 256>>>(W2);
    h_kernel<<<HALF_TOKENS / 32, 256>>>(x, theta, W1, b1, 0);

    if (ok) {
        cudaEventRecord(eFork, 0);
        cudaStreamWaitEvent(s2, eFork, 0);
        gemm_kernel<<<ggrid, GT, SMEM_TOTAL, s2>>>(b2, out, 0);           // half0 (side)
        h_kernel<<<HALF_TOKENS / 32, 256>>>(x, theta, W1, b1, HALF_TOKENS); // overlaps
        gemm_kernel<<<ggrid, GT, SMEM_TOTAL>>>(b2, out, HALF_TOKENS);     // half1
        cudaEventRecord(eJoin, s2);
        cudaStreamWaitEvent(0, eJoin, 0);
    } else {
        h_kernel<<<HALF_TOKENS / 32, 256>>>(x, theta, W1, b1, HALF_TOKENS);
        gemm_kernel<<<ggrid, GT, SMEM_TOTAL>>>(b2, out, 0);
        gemm_kernel<<<ggrid, GT, SMEM_TOTAL>>>(b2, out, HALF_TOKENS);
    }
}

// round 15
// speedup vs baseline: 1.0334x; 1.0334x over previous
#include <cuda_runtime.h>
#include <cuda_fp16.h>
#include <cstdint>
#include <math.h>

#define TOKENS 32768
#define EDIM   512
#define FFN    2048
#define NQ     8
#define HALF_TOKENS (TOKENS / 2)

// ---------------- scratch (device globals: allowed) ----------------
__device__ __half g_W2h[EDIM * FFN];           // 2 MB
__device__ __half g_Hh[(size_t)TOKENS * FFN];  // 128 MB

// ---------------- prep: W2 -> fp16 ----------------
__global__ void __launch_bounds__(256) prep_kernel(const float* __restrict__ W2) {
    int i = (blockIdx.x * blockDim.x + threadIdx.x) * 4;
    float4 v = *reinterpret_cast<const float4*>(W2 + i);
    __half2* dst = reinterpret_cast<__half2*>(g_W2h + i);
    dst[0] = __floats2half2_rn(v.x, v.y);
    dst[1] = __floats2half2_rn(v.z, v.w);
}

// ---------------- h kernel (R12 proven scalar version) ----------------
__global__ void __launch_bounds__(256)
h_kernel(const float* __restrict__ x, const float* __restrict__ theta,
         const float* __restrict__ W1, const float* __restrict__ b1, int mbase)
{
    __shared__ float qv[32][8];
    const int tid = threadIdx.x;
    const int m0  = mbase + blockIdx.x * 32;

    {
        int m = tid >> 3, q = tid & 7;
        qv[m][q] = cosf(x[(size_t)(m0 + m) * EDIM + q]) * cosf(theta[q]);
    }
    __syncthreads();

    const int f0 = tid * 8;
    float w[8][8];
    #pragma unroll
    for (int i = 0; i < 8; i++) {
        const float4* p = reinterpret_cast<const float4*>(W1 + (size_t)(f0 + i) * NQ);
        float4 a = p[0], b = p[1];
        w[i][0] = a.x; w[i][1] = a.y; w[i][2] = a.z; w[i][3] = a.w;
        w[i][4] = b.x; w[i][5] = b.y; w[i][6] = b.z; w[i][7] = b.w;
    }
    float bb[8];
    {
        const float4* p = reinterpret_cast<const float4*>(b1 + f0);
        float4 a = p[0], b = p[1];
        bb[0] = a.x; bb[1] = a.y; bb[2] = a.z; bb[3] = a.w;
        bb[4] = b.x; bb[5] = b.y; bb[6] = b.z; bb[7] = b.w;
    }

    for (int m = 0; m < 32; m++) {
        float q0 = qv[m][0], q1 = qv[m][1], q2 = qv[m][2], q3 = qv[m][3];
        float q4 = qv[m][4], q5 = qv[m][5], q6 = qv[m][6], q7 = qv[m][7];
        float acc[8];
        #pragma unroll
        for (int i = 0; i < 8; i++) {
            float s = bb[i];
            s += q0 * w[i][0]; s += q1 * w[i][1];
            s += q2 * w[i][2]; s += q3 * w[i][3];
            s += q4 * w[i][4]; s += q5 * w[i][5];
            s += q6 * w[i][6]; s += q7 * w[i][7];
            acc[i] = fmaxf(s, 0.0f);
        }
        uint32_t p[4];
        #pragma unroll
        for (int i = 0; i < 4; i++)
            asm("cvt.rn.f16x2.f32 %0, %1, %2;" : "=r"(p[i])
                : "f"(acc[2 * i + 1]), "f"(acc[2 * i]));   // lo = even index
        __half* dst = g_Hh + (size_t)(m0 + m) * FFN + f0;
        asm volatile("st.global.v4.b32 [%0], {%1,%2,%3,%4};"
                     :: "l"(dst), "r"(p[0]), "r"(p[1]), "r"(p[2]), "r"(p[3]) : "memory");
    }
}

// ---------------- GEMM: out = H @ W2^T + b2 (unchanged proven core) ----------------
#define BM 128
#define BN 128
#define BK 64
#define GT 256
#define STAGES 3
#define CHUNKS (FFN / BK)   // 32
#define STAGE_BYTES 32768
#define SMEM_TOTAL (STAGES * STAGE_BYTES)   // 96 KB

__device__ __forceinline__ uint32_t s2u(const void* p) {
    uint32_t a;
    asm("{ .reg .u64 t; cvta.to.shared.u64 t, %1; cvt.u32.u64 %0, t; }" : "=r"(a) : "l"(p));
    return a;
}
#define LDSM_X4(r, addr) \
    asm volatile("ldmatrix.sync.aligned.m8n8.x4.shared.b16 {%0,%1,%2,%3}, [%4];" \
        : "=r"((r)[0]), "=r"((r)[1]), "=r"((r)[2]), "=r"((r)[3]) : "r"(addr))

__device__ __forceinline__ void mma_f16(float* d, const uint32_t* a, uint32_t b0, uint32_t b1) {
    asm volatile(
        "mma.sync.aligned.m16n8k16.row.col.f32.f16.f16.f32 "
        "{%0,%1,%2,%3}, {%4,%5,%6,%7}, {%8,%9}, {%0,%1,%2,%3};"
        : "+f"(d[0]), "+f"(d[1]), "+f"(d[2]), "+f"(d[3])
        : "r"(a[0]), "r"(a[1]), "r"(a[2]), "r"(a[3]), "r"(b0), "r"(b1));
}

__global__ void __launch_bounds__(GT, 2)
gemm_kernel(const float* __restrict__ b2, float* __restrict__ out, int mbase)
{
    extern __shared__ unsigned char smem[];
    const uint32_t sb = s2u(smem);
    const int tid  = threadIdx.x;
    const int warp = tid >> 5;
    const int lane = tid & 31;
    const int g  = lane >> 2;
    const int tg = lane & 3;

    const int m0 = mbase + blockIdx.x * BM;
    const int n0 = blockIdx.y * BN;

    const int wm = (warp >> 2) * 64;
    const int wn = (warp & 3) * 32;

    const int ar  = (lane & 7) + ((lane >> 3) & 1) * 8;
    const int ac8 = ((lane >> 4) & 1) * 8;
    const int br  = (lane & 7) + ((lane >> 4) & 1) * 8;
    const int bc8 = ((lane >> 3) & 1) * 8;

    float acc[4][4][4];
    #pragma unroll
    for (int mi = 0; mi < 4; mi++)
        #pragma unroll
        for (int ni = 0; ni < 4; ni++)
            #pragma unroll
            for (int r = 0; r < 4; r++)
                acc[mi][ni][r] = 0.0f;

    auto produce = [&](int c, int slot) {
        const uint32_t aB = sb + slot * STAGE_BYTES;
        const uint32_t bB = aB + 16384;
        #pragma unroll
        for (int i = 0; i < 8; i++) {
            int idx = tid + i * GT;
            int row = (idx >> 3) & 127;
            int kq  = idx & 7;
            uint32_t off = (uint32_t)row * 128 + (((uint32_t)kq * 16) ^ ((row & 7) << 4));
            if (idx < 1024) {
                const __half* src = g_Hh + (size_t)(m0 + row) * FFN + c * BK + kq * 8;
                asm volatile("cp.async.cg.shared.global [%0], [%1], 16;"
                             :: "r"(aB + off), "l"(src) : "memory");
            } else {
                const __half* src = g_W2h + (size_t)(n0 + row) * FFN + c * BK + kq * 8;
                asm volatile("cp.async.cg.shared.global [%0], [%1], 16;"
                             :: "r"(bB + off), "l"(src) : "memory");
            }
        }
        asm volatile("cp.async.commit_group;" ::: "memory");
    };

    auto consume = [&](int slot) {
        const uint32_t aB = sb + slot * STAGE_BYTES;
        const uint32_t bB = aB + 16384;
        #pragma unroll
        for (int ks = 0; ks < 4; ks++) {
            int kb = ks * 16;
            uint32_t afr[4][4];
            #pragma unroll
            for (int mi = 0; mi < 4; mi++) {
                int r = wm + mi * 16 + ar;
                uint32_t cb = (uint32_t)(kb + ac8) * 2;
                LDSM_X4(afr[mi], aB + (uint32_t)r * 128 + (cb ^ ((r & 7) << 4)));
            }
            uint32_t bfr[2][4];
            #pragma unroll
            for (int p = 0; p < 2; p++) {
                int n = wn + p * 16 + br;
                uint32_t cb = (uint32_t)(kb + bc8) * 2;
                LDSM_X4(bfr[p], bB + (uint32_t)n * 128 + (cb ^ ((n & 7) << 4)));
            }
            #pragma unroll
            for (int ni = 0; ni < 4; ni++) {
                uint32_t b0 = bfr[ni >> 1][(ni & 1) * 2 + 0];
                uint32_t b1 = bfr[ni >> 1][(ni & 1) * 2 + 1];
                #pragma unroll
                for (int mi = 0; mi < 4; mi++)
                    mma_f16(acc[mi][ni], afr[mi], b0, b1);
            }
        }
    };

    produce(0, 0);
    produce(1, 1);

    #pragma unroll 1
    for (int c = 0; c < CHUNKS - 1; c++) {
        asm volatile("cp.async.wait_group 1;" ::: "memory");
        __syncthreads();
        consume(c % STAGES);
        if (c + 2 < CHUNKS) produce(c + 2, (c + 2) % STAGES);
    }
    asm volatile("cp.async.wait_group 0;" ::: "memory");
    __syncthreads();
    consume((CHUNKS - 1) % STAGES);

    #pragma unroll
    for (int mi = 0; mi < 4; mi++) {
        #pragma unroll
        for (int ni = 0; ni < 4; ni++) {
            int row = m0 + wm + mi * 16 + g;
            int col = n0 + wn + ni * 8 + 2 * tg;
            float b2a = b2[col];
            float b2b = b2[col + 1];
            float2 v0 = make_float2(acc[mi][ni][0] + b2a, acc[mi][ni][1] + b2b);
            float2 v1 = make_float2(acc[mi][ni][2] + b2a, acc[mi][ni][3] + b2b);
            *reinterpret_cast<float2*>(out + (size_t)row * EDIM + col)       = v0;
            *reinterpret_cast<float2*>(out + (size_t)(row + 8) * EDIM + col) = v1;
        }
    }
}

extern "C" void kernel_launch(void* const* d_in, const int* in_sizes, int n_in,
                              void* d_out, int out_size) {
    const float* x     = (const float*)d_in[0];
    const float* theta = (const float*)d_in[1];
    const float* W1    = (const float*)d_in[2];
    const float* b1    = (const float*)d_in[3];
    const float* W2    = (const float*)d_in[4];
    const float* b2    = (const float*)d_in[5];
    float* out = (float*)d_out;

    cudaFuncSetAttribute(gemm_kernel,
                         cudaFuncAttributeMaxDynamicSharedMemorySize, SMEM_TOTAL);

    dim3 ggrid(HALF_TOKENS / BM, EDIM / BN);   // (128, 4) per half

    // Fork-join DAG (capture-legal, proven in R13):
    //   s2:   prep ──────────────► gemm0(half0)   [needs prep + h0]
    //   main: h0 ─► h1 ───────────► gemm1(half1)  [needs prep + h1]
    // gemm0 and gemm1 are independent -> co-resident, fill each other's tails.
    cudaStream_t s2 = nullptr;
    cudaEvent_t eFork = nullptr, ePrep = nullptr, eH0 = nullptr, eJoin = nullptr;
    bool ok = (cudaStreamCreateWithFlags(&s2, cudaStreamNonBlocking) == cudaSuccess)
           && (cudaEventCreateWithFlags(&eFork, cudaEventDisableTiming) == cudaSuccess)
           && (cudaEventCreateWithFlags(&ePrep, cudaEventDisableTiming) == cudaSuccess)
           && (cudaEventCreateWithFlags(&eH0,   cudaEventDisableTiming) == cudaSuccess)
           && (cudaEventCreateWithFlags(&eJoin, cudaEventDisableTiming) == cudaSuccess);

    if (ok) {
        cudaEventRecord(eFork, 0);
        cudaStreamWaitEvent(s2, eFork, 0);
        prep_kernel<<<(EDIM * FFN / 4) / 256, 256, 0, s2>>>(W2);       // s2: prep
        cudaEventRecord(ePrep, s2);

        h_kernel<<<HALF_TOKENS / 32, 256>>>(x, theta, W1, b1, 0);      // main: h0 (|| prep)
        cudaEventRecord(eH0, 0);

        cudaStreamWaitEvent(s2, eH0, 0);
        gemm_kernel<<<ggrid, GT, SMEM_TOTAL, s2>>>(b2, out, 0);        // s2: gemm0
        cudaEventRecord(eJoin, s2);

        h_kernel<<<HALF_TOKENS / 32, 256>>>(x, theta, W1, b1, HALF_TOKENS); // main: h1 (|| gemm0)
        cudaStreamWaitEvent(0, ePrep, 0);
        gemm_kernel<<<ggrid, GT, SMEM_TOTAL>>>(b2, out, HALF_TOKENS);  // main: gemm1 (|| gemm0)
        cudaStreamWaitEvent(0, eJoin, 0);
    } else {
        prep_kernel<<<(EDIM * FFN / 4) / 256, 256>>>(W2);
        h_kernel<<<HALF_TOKENS / 32, 256>>>(x, theta, W1, b1, 0);
        h_kernel<<<HALF_TOKENS / 32, 256>>>(x, theta, W1, b1, HALF_TOKENS);
        gemm_kernel<<<ggrid, GT, SMEM_TOTAL>>>(b2, out, 0);
        gemm_kernel<<<ggrid, GT, SMEM_TOTAL>>>(b2, out, HALF_TOKENS);
    }
}